// round 2
// baseline (speedup 1.0000x reference)
#include <cuda_runtime.h>
#include <math.h>

#define D   512
#define MT  64     // rows per block
#define KT  128    // codes per K-tile
#define DT  64     // depth per smem stage
#define TR  16     // thread rows
#define TC  16     // thread cols
#define R   4      // rows per thread
#define C   8      // codes per thread
#define PITCH 68   // DT + 4 pad (conflict-free float4 LDS)

#define MAXN 32768
#define MAXK 8192

__device__ float g_csq[MAXK];
__device__ float g_zsq[MAXN];
__device__ float g_dmin[MAXN];
__device__ float g_H[MAXN];
__device__ int   g_idx[MAXN];
__device__ float g_loss;

// -------- per-row sum of squares (one warp per row) --------
__global__ void sumsq_kernel(const float* __restrict__ src, int rows, int which) {
    int warp = (blockIdx.x * blockDim.x + threadIdx.x) >> 5;
    int lane = threadIdx.x & 31;
    if (warp >= rows) return;
    const float4* p = (const float4*)(src + (size_t)warp * D);
    float acc = 0.f;
#pragma unroll
    for (int i = 0; i < 4; ++i) {
        float4 v = p[lane + i * 32];
        acc += v.x * v.x + v.y * v.y + v.z * v.z + v.w * v.w;
    }
#pragma unroll
    for (int off = 16; off; off >>= 1) acc += __shfl_down_sync(0xffffffffu, acc, off);
    if (lane == 0) {
        if (which) g_csq[warp] = acc; else g_zsq[warp] = acc;
    }
}

// -------- fused cdist + argmin + online softmax entropy --------
__global__ void __launch_bounds__(256, 2)
dist_kernel(const float* __restrict__ z, const float* __restrict__ cb, int N, int K) {
    extern __shared__ float sm[];
    float* zt = sm;                 // [MT][PITCH]
    float* ct = sm + MT * PITCH;    // [KT][PITCH]

    int t  = threadIdx.x;
    int tr = t / TC;
    int tc = t % TC;
    int n0 = blockIdx.x * MT;

    int ldrow = t >> 4;             // tile-load row
    int ldcol = (t & 15) * 4;       // tile-load col (floats)

    float dmin[R], s[R], tt[R];
    int   arg[R];
    float zsq_r[R];
#pragma unroll
    for (int r = 0; r < R; ++r) {
        dmin[r] = 1e30f; s[r] = 0.f; tt[r] = 0.f; arg[r] = 0;
        zsq_r[r] = __ldg(&g_zsq[n0 + tr * R + r]);
    }

    for (int k0 = 0; k0 < K; k0 += KT) {
        float acc[R][C];
#pragma unroll
        for (int r = 0; r < R; ++r)
#pragma unroll
            for (int c = 0; c < C; ++c) acc[r][c] = 0.f;

        for (int d0 = 0; d0 < D; d0 += DT) {
            __syncthreads();
            // stage z tile [MT][DT]
#pragma unroll
            for (int i = 0; i < MT / 16; ++i) {
                float4 v = *(const float4*)(z + (size_t)(n0 + ldrow + i * 16) * D + d0 + ldcol);
                *(float4*)(zt + (ldrow + i * 16) * PITCH + ldcol) = v;
            }
            // stage codebook tile [KT][DT]
#pragma unroll
            for (int i = 0; i < KT / 16; ++i) {
                float4 v = *(const float4*)(cb + (size_t)(k0 + ldrow + i * 16) * D + d0 + ldcol);
                *(float4*)(ct + (ldrow + i * 16) * PITCH + ldcol) = v;
            }
            __syncthreads();

#pragma unroll
            for (int dq = 0; dq < DT / 4; ++dq) {
                float4 zf[R], cf[C];
#pragma unroll
                for (int r = 0; r < R; ++r)
                    zf[r] = *(const float4*)(zt + (tr * R + r) * PITCH + dq * 4);
#pragma unroll
                for (int c = 0; c < C; ++c)
                    cf[c] = *(const float4*)(ct + (tc + c * TC) * PITCH + dq * 4);
#pragma unroll
                for (int r = 0; r < R; ++r)
#pragma unroll
                    for (int c = 0; c < C; ++c) {
                        acc[r][c] += zf[r].x * cf[c].x;
                        acc[r][c] += zf[r].y * cf[c].y;
                        acc[r][c] += zf[r].z * cf[c].z;
                        acc[r][c] += zf[r].w * cf[c].w;
                    }
            }
        }

        // epilogue: d = sqrt(max(zsq + csq - 2*dot, 0)); online min/softmax
#pragma unroll
        for (int c = 0; c < C; ++c) {
            int code = k0 + tc + c * TC;
            float csq = __ldg(&g_csq[code]);
#pragma unroll
            for (int r = 0; r < R; ++r) {
                float d2 = zsq_r[r] + csq - 2.f * acc[r][c];
                float dd = sqrtf(fmaxf(d2, 0.f));
                float nm = fminf(dmin[r], dd);
                float sc = __expf(nm - dmin[r]);   // 1 if no new min
                float e  = __expf(nm - dd);        // term weight
                s[r]  = s[r]  * sc + e;
                tt[r] = tt[r] * sc + e * dd;
                if (dd < dmin[r]) arg[r] = code;
                dmin[r] = nm;
            }
        }
    }

    // reduce across the 16 lanes (tc) sharing each row; lane tc==0 writes
#pragma unroll
    for (int r = 0; r < R; ++r) {
#pragma unroll
        for (int off = 8; off; off >>= 1) {
            float dm2 = __shfl_down_sync(0xffffffffu, dmin[r], off, 16);
            float s2  = __shfl_down_sync(0xffffffffu, s[r],    off, 16);
            float t2  = __shfl_down_sync(0xffffffffu, tt[r],   off, 16);
            int   a2  = __shfl_down_sync(0xffffffffu, arg[r],  off, 16);
            float nm  = fminf(dmin[r], dm2);
            float sc1 = __expf(nm - dmin[r]);
            float sc2 = __expf(nm - dm2);
            s[r]  = s[r]  * sc1 + s2 * sc2;
            tt[r] = tt[r] * sc1 + t2 * sc2;
            arg[r] = (dm2 < dmin[r]) ? a2 : arg[r];
            dmin[r] = nm;
        }
        if (tc == 0) {
            int row = n0 + tr * R + r;
            g_dmin[row] = dmin[r];
            g_idx[row]  = arg[r];
            // H = lse + sum p*d ; lse = log(s) - dmin
            g_H[row] = __logf(s[r]) - dmin[r] + tt[r] / s[r];
        }
    }
}

// -------- scalar loss reduction --------
__global__ void loss_kernel(int N) {
    __shared__ float sd[1024], sh[1024];
    int t = threadIdx.x;
    float a = 0.f, b = 0.f;
    for (int i = t; i < N; i += 1024) { a += g_dmin[i]; b += g_H[i]; }
    sd[t] = a; sh[t] = b;
    __syncthreads();
    for (int off = 512; off; off >>= 1) {
        if (t < off) { sd[t] += sd[t + off]; sh[t] += sh[t + off]; }
        __syncthreads();
    }
    if (t == 0) g_loss = sd[0] / (float)N + 0.1f * sh[0] / (float)N;
}

// -------- outputs: gather quantized, deviation>eps, broadcast loss --------
__global__ void out_kernel(const float* __restrict__ cb, const float* __restrict__ yb,
                           const float* __restrict__ et, float* __restrict__ out, int N) {
    int warp = (blockIdx.x * blockDim.x + threadIdx.x) >> 5;
    int lane = threadIdx.x & 31;
    if (warp >= N) return;
    int idx = g_idx[warp];
    const float4* crow = (const float4*)(cb + (size_t)idx * D);
    const float4* yrow = (const float4*)(yb + (size_t)warp * D);
    float4*       qrow = (float4*)(out + (size_t)warp * D);
    float acc = 0.f;
#pragma unroll
    for (int i = 0; i < 4; ++i) {
        float4 cv = crow[lane + i * 32];
        float4 yv = yrow[lane + i * 32];
        qrow[lane + i * 32] = cv;
        float dx = cv.x - yv.x, dy = cv.y - yv.y, dz = cv.z - yv.z, dw = cv.w - yv.w;
        acc += dx * dx + dy * dy + dz * dz + dw * dw;
    }
#pragma unroll
    for (int off = 16; off; off >>= 1) acc += __shfl_down_sync(0xffffffffu, acc, off);
    if (lane == 0) {
        float dev = sqrtf(acc);
        out[(size_t)N * D + warp]     = g_loss;                                  // quant_loss (w=1)
        out[(size_t)N * D + N + warp] = et[warp] + (dev > 0.01f ? 1.0f : 0.0f);  // error_times
    }
}

extern "C" void kernel_launch(void* const* d_in, const int* in_sizes, int n_in,
                              void* d_out, int out_size) {
    const float* z  = (const float*)d_in[0];
    const float* yb = (const float*)d_in[1];
    const float* et = (const float*)d_in[2];
    const float* cb = (const float*)d_in[3];
    int N = in_sizes[0] / D;
    int K = in_sizes[3] / D;
    float* out = (float*)d_out;

    const int smem = (MT + KT) * PITCH * (int)sizeof(float);   // 52224 B
    cudaFuncSetAttribute(dist_kernel, cudaFuncAttributeMaxDynamicSharedMemorySize, smem);

    sumsq_kernel<<<(N + 7) / 8, 256>>>(z, N, 0);
    sumsq_kernel<<<(K + 7) / 8, 256>>>(cb, K, 1);
    dist_kernel<<<N / MT, 256, smem>>>(z, cb, N, K);
    loss_kernel<<<1, 1024>>>(N);
    out_kernel<<<(N + 7) / 8, 256>>>(cb, yb, et, out, N);
}

// round 4
// speedup vs baseline: 4.1700x; 4.1700x over previous
#include <cuda_runtime.h>
#include <cuda_bf16.h>
#include <math.h>
#include <stdint.h>

#define D    512
#define NTOK 32768
#define KCB  8192
#define MT   128              // rows per CTA
#define NT   128              // codes per n-iter
#define KC   64               // k per chunk
#define NITER ((KCB / NT) * (D / KC))   // 64 * 8 = 512
#define A_BYTES (MT * D * 2)            // 131072
#define B_STAGE (NT * KC * 2 * 2)       // 32768 (hi+lo)
#define SMEM_SZ (A_BYTES + 2 * B_STAGE) // 196608

// ---------------- device globals ----------------
__device__ __nv_bfloat16 g_zh[(size_t)NTOK * D];
__device__ __nv_bfloat16 g_ch[(size_t)KCB * D];
__device__ __nv_bfloat16 g_cl[(size_t)KCB * D];
__device__ float g_zsq[NTOK];
__device__ float g_csq[KCB];
__device__ float g_dmin[NTOK];
__device__ float g_H[NTOK];
__device__ int   g_c0[NTOK], g_c1[NTOK], g_c2[NTOK];
__device__ int   g_idx[NTOK];
__device__ float g_loss;

// ---------------- helpers ----------------
__device__ __forceinline__ uint32_t smem_u32(const void* p) {
    uint32_t a;
    asm("{ .reg .u64 t; cvta.to.shared.u64 t, %1; cvt.u32.u64 %0, t; }" : "=r"(a) : "l"(p));
    return a;
}
__device__ __forceinline__ void cp16(uint32_t s, const void* g) {
    asm volatile("cp.async.cg.shared.global [%0], [%1], 16;" :: "r"(s), "l"(g));
}
#define CP_COMMIT() asm volatile("cp.async.commit_group;" ::: "memory")
#define CP_WAIT0()  asm volatile("cp.async.wait_group 0;" ::: "memory")

__device__ __forceinline__ void ldsm4(uint32_t& r0, uint32_t& r1, uint32_t& r2, uint32_t& r3, uint32_t a) {
    asm volatile("ldmatrix.sync.aligned.m8n8.x4.shared.b16 {%0,%1,%2,%3}, [%4];"
                 : "=r"(r0), "=r"(r1), "=r"(r2), "=r"(r3) : "r"(a));
}
__device__ __forceinline__ void mma16816(float* c, uint32_t a0, uint32_t a1, uint32_t a2, uint32_t a3,
                                         uint32_t b0, uint32_t b1) {
    asm volatile("mma.sync.aligned.m16n8k16.row.col.f32.bf16.bf16.f32 "
                 "{%0,%1,%2,%3},{%4,%5,%6,%7},{%8,%9},{%0,%1,%2,%3};"
                 : "+f"(c[0]), "+f"(c[1]), "+f"(c[2]), "+f"(c[3])
                 : "r"(a0), "r"(a1), "r"(a2), "r"(a3), "r"(b0), "r"(b1));
}

// exp(x) for x in [-70, 0], FMA-pipe only (no MUFU), rel err ~4e-5
__device__ __forceinline__ float expapx(float x) {
    float y = fmaf(x, 1.442695041f, 12582912.f);
    int ib = __float_as_int(y);
    float n = y - 12582912.f;
    float f = fmaf(x, 1.442695041f, -n);
    float p = fmaf(f, 0.009618130f, 0.055504110f);
    p = fmaf(f, p, 0.240226507f);
    p = fmaf(f, p, 0.693147181f);
    p = fmaf(f, p, 1.0f);
    return __int_as_float(__float_as_int(p) + (ib << 23));
}

// ---------------- split: fp32 -> bf16 (hi [, lo]) + row sumsq ----------------
__global__ void split_kernel(const float* __restrict__ src, int rows, int which) {
    int warp = (blockIdx.x * blockDim.x + threadIdx.x) >> 5;
    int lane = threadIdx.x & 31;
    if (warp >= rows) return;
    const float4* p = (const float4*)(src + (size_t)warp * D);
    float acc = 0.f;
#pragma unroll
    for (int i = 0; i < 4; ++i) {
        float4 v = p[lane + i * 32];
        acc += v.x * v.x + v.y * v.y + v.z * v.z + v.w * v.w;
        float xs[4] = {v.x, v.y, v.z, v.w};
        size_t base = (size_t)warp * D + (lane + i * 32) * 4;
#pragma unroll
        for (int j = 0; j < 4; ++j) {
            __nv_bfloat16 h = __float2bfloat16(xs[j]);
            if (which) {
                g_ch[base + j] = h;
                g_cl[base + j] = __float2bfloat16(xs[j] - __bfloat162float(h));
            } else {
                g_zh[base + j] = h;
            }
        }
    }
#pragma unroll
    for (int off = 16; off; off >>= 1) acc += __shfl_down_sync(0xffffffffu, acc, off);
    if (lane == 0) { if (which) g_csq[warp] = acc; else g_zsq[warp] = acc; }
}

// ---------------- B chunk loader ----------------
__device__ __forceinline__ void load_b(uint32_t sb, int iter, int tid) {
    int nt = iter >> 3, kc = iter & 7;
    uint32_t st = sb + A_BYTES + (uint32_t)(iter & 1) * B_STAGE;
    const __nv_bfloat16* bh = g_ch + (size_t)(nt * NT) * D + kc * KC;
    const __nv_bfloat16* bl = g_cl + (size_t)(nt * NT) * D + kc * KC;
#pragma unroll
    for (int i = 0; i < 4; ++i) {
        int q = tid + i * 256;
        int r = q >> 3, c16 = q & 7;
        uint32_t off = (uint32_t)(r * 128 + ((c16 * 16) ^ ((r & 7) << 4)));
        cp16(st + off, bh + (size_t)r * D + c16 * 8);
        cp16(st + 16384 + off, bl + (size_t)r * D + c16 * 8);
    }
}

// ---------------- main HMMA GEMM + fused epilogue ----------------
__global__ void __launch_bounds__(256, 1) gemm_kernel() {
    extern __shared__ __align__(1024) char sm[];
    uint32_t sb = smem_u32(sm);
    int tid = threadIdx.x, lane = tid & 31, wid = tid >> 5;
    int wm = wid & 3, wn = wid >> 2;          // warp grid 4(M) x 2(N); warp tile 32x64
    int n0 = blockIdx.x * MT;

    // ---- load A (z hi, 128x512 bf16) resident, swizzled chunks of [128][64]
    {
        const __nv_bfloat16* zb = g_zh + (size_t)n0 * D;
#pragma unroll
        for (int i = 0; i < 32; ++i) {
            int q = tid + i * 256;
            int kc = q >> 10, u = q & 1023, r = u >> 3, c16 = u & 7;
            uint32_t so = sb + (uint32_t)(kc * 16384 + r * 128 + ((c16 * 16) ^ ((r & 7) << 4)));
            cp16(so, zb + (size_t)r * D + kc * KC + c16 * 8);
        }
    }
    load_b(sb, 0, tid);
    CP_COMMIT();

    // per-thread per-row state: s = mt*2 + h  (4 rows per thread)
    float m1[4], ss[4], tt[4], zs[4];
    float tv[4][3]; int ti[4][3];
#pragma unroll
    for (int s = 0; s < 4; ++s) {
        m1[s] = 60.f; ss[s] = 0.f; tt[s] = 0.f;
        tv[s][0] = tv[s][1] = tv[s][2] = 1e30f;
        ti[s][0] = ti[s][1] = ti[s][2] = 0;
        int row = n0 + wm * 32 + (s >> 1) * 16 + (lane >> 2) + (s & 1) * 8;
        zs[s] = g_zsq[row];
    }

    float acc[2][8][4];
    // ldsm lane address components (constant across loop)
    int laneA_r[2], laneB_r[4];
#pragma unroll
    for (int mt = 0; mt < 2; ++mt)
        laneA_r[mt] = wm * 32 + mt * 16 + (lane & 7) + ((lane >> 3) & 1) * 8;
#pragma unroll
    for (int p = 0; p < 4; ++p)
        laneB_r[p] = wn * 64 + (p * 2 + ((lane >> 4) & 1)) * 8 + (lane & 7);
    int byteA = ((lane >> 4) & 1) * 16;
    int byteB = ((lane >> 3) & 1) * 16;

    for (int it = 0; it < NITER; ++it) {
        CP_WAIT0();
        __syncthreads();
        if (it + 1 < NITER) { load_b(sb, it + 1, tid); CP_COMMIT(); }

        int kc = it & 7;
        uint32_t abase = sb + kc * 16384;
        uint32_t bbase = sb + A_BYTES + (uint32_t)(it & 1) * B_STAGE;

        if (kc == 0) {
#pragma unroll
            for (int mt = 0; mt < 2; ++mt)
#pragma unroll
                for (int n = 0; n < 8; ++n)
#pragma unroll
                    for (int q = 0; q < 4; ++q) acc[mt][n][q] = 0.f;
        }

#pragma unroll
        for (int j = 0; j < 4; ++j) {
            uint32_t a[2][4];
#pragma unroll
            for (int mt = 0; mt < 2; ++mt) {
                int r = laneA_r[mt];
                uint32_t ad = abase + (uint32_t)(r * 128 + ((j * 32 + byteA) ^ ((r & 7) << 4)));
                ldsm4(a[mt][0], a[mt][1], a[mt][2], a[mt][3], ad);
            }
            uint32_t bh[8][2], bl[8][2];
#pragma unroll
            for (int p = 0; p < 4; ++p) {
                int r = laneB_r[p];
                uint32_t off = (uint32_t)(r * 128 + ((j * 32 + byteB) ^ ((r & 7) << 4)));
                ldsm4(bh[2 * p][0], bh[2 * p][1], bh[2 * p + 1][0], bh[2 * p + 1][1], bbase + off);
                ldsm4(bl[2 * p][0], bl[2 * p][1], bl[2 * p + 1][0], bl[2 * p + 1][1], bbase + 16384 + off);
            }
#pragma unroll
            for (int mt = 0; mt < 2; ++mt)
#pragma unroll
                for (int n = 0; n < 8; ++n) {
                    mma16816(acc[mt][n], a[mt][0], a[mt][1], a[mt][2], a[mt][3], bh[n][0], bh[n][1]);
                    mma16816(acc[mt][n], a[mt][0], a[mt][1], a[mt][2], a[mt][3], bl[n][0], bl[n][1]);
                }
        }

        if (kc == 7) {                        // fused epilogue for this 128-code tile
            int nt = it >> 3;
            int colbase = nt * 128 + wn * 64 + (lane & 3) * 2;
            float csv[16];
#pragma unroll
            for (int n = 0; n < 8; ++n) {
                csv[2 * n]     = __ldg(g_csq + colbase + n * 8);
                csv[2 * n + 1] = __ldg(g_csq + colbase + n * 8 + 1);
            }
#pragma unroll
            for (int mt = 0; mt < 2; ++mt)
#pragma unroll
                for (int n = 0; n < 8; ++n)
#pragma unroll
                    for (int h = 0; h < 2; ++h)
#pragma unroll
                        for (int q = 0; q < 2; ++q) {
                            int s = mt * 2 + h;
                            float dot = acc[mt][n][h * 2 + q];
                            int code = colbase + n * 8 + q;
                            float d2 = fmaf(-2.f, dot, zs[s] + csv[2 * n + q]);
                            d2 = fmaxf(d2, 1e-6f);
                            float y = __int_as_float(0x5f3759df - (__float_as_int(d2) >> 1));
                            float t2 = y * y; y = y * fmaf(-0.5f * d2, t2, 1.5f);
                            t2 = y * y;       y = y * fmaf(-0.5f * d2, t2, 1.5f);
                            float d = d2 * y;              // sqrt(d2), rel err ~5e-6
                            if (d2 < tv[s][2]) {           // top-3 (rare path)
                                if (d2 < tv[s][1]) {
                                    tv[s][2] = tv[s][1]; ti[s][2] = ti[s][1];
                                    if (d2 < tv[s][0]) {
                                        tv[s][1] = tv[s][0]; ti[s][1] = ti[s][0];
                                        tv[s][0] = d2; ti[s][0] = code;
                                    } else { tv[s][1] = d2; ti[s][1] = code; }
                                } else { tv[s][2] = d2; ti[s][2] = code; }
                            }
                            bool nm = d < m1[s];
                            float x = nm ? (d - m1[s]) : (m1[s] - d);
                            float e = expapx(x);
                            if (nm) {
                                ss[s] = fmaf(ss[s], e, 1.f);
                                tt[s] = fmaf(tt[s], e, d);
                                m1[s] = d;
                            } else {
                                ss[s] += e;
                                tt[s] = fmaf(e, d, tt[s]);
                            }
                        }
        }
    }

    // ---- merge 8 partials per row via smem (reuse B area)
    __syncthreads();
    float* msm = (float*)(sm + A_BYTES);
    int*   mim = (int*)msm;
#pragma unroll
    for (int s = 0; s < 4; ++s) {
        int row_local = wm * 32 + (s >> 1) * 16 + (lane >> 2) + (s & 1) * 8;
        int base = (row_local * 8 + wn * 4 + (lane & 3)) * 9;
        msm[base + 0] = m1[s]; msm[base + 1] = ss[s]; msm[base + 2] = tt[s];
        msm[base + 3] = tv[s][0]; msm[base + 4] = tv[s][1]; msm[base + 5] = tv[s][2];
        mim[base + 6] = ti[s][0]; mim[base + 7] = ti[s][1]; mim[base + 8] = ti[s][2];
    }
    __syncthreads();
    if (tid < 128) {
        int row = tid;
        float M = 1e30f;
#pragma unroll
        for (int j = 0; j < 8; ++j) M = fminf(M, msm[(row * 8 + j) * 9]);
        float S = 0.f, T = 0.f;
        float bv0 = 1e30f, bv1 = 1e30f, bv2 = 1e30f;
        int bi0 = 0, bi1 = 0, bi2 = 0;
#pragma unroll
        for (int j = 0; j < 8; ++j) {
            int base = (row * 8 + j) * 9;
            float fct = __expf(M - msm[base + 0]);
            S = fmaf(msm[base + 1], fct, S);
            T = fmaf(msm[base + 2], fct, T);
#pragma unroll
            for (int k = 0; k < 3; ++k) {
                float v = msm[base + 3 + k];
                int   ix = mim[base + 6 + k];
                if (v < bv2) {
                    if (v < bv1) {
                        bv2 = bv1; bi2 = bi1;
                        if (v < bv0) { bv1 = bv0; bi1 = bi0; bv0 = v; bi0 = ix; }
                        else         { bv1 = v;  bi1 = ix; }
                    } else { bv2 = v; bi2 = ix; }
                }
            }
        }
        int grow = n0 + row;
        g_H[grow]  = __logf(S) - M + T / S;
        g_c0[grow] = bi0; g_c1[grow] = bi1; g_c2[grow] = bi2;
    }
}

// ---------------- exact fp32 rescore of top-3 candidates ----------------
__global__ void fixup_kernel(const float* __restrict__ z, const float* __restrict__ cb, int N) {
    int warp = (blockIdx.x * blockDim.x + threadIdx.x) >> 5;
    int lane = threadIdx.x & 31;
    if (warp >= N) return;
    int c0 = g_c0[warp], c1 = g_c1[warp], c2 = g_c2[warp];
    const float4* zr = (const float4*)(z + (size_t)warp * D);
    const float4* p0 = (const float4*)(cb + (size_t)c0 * D);
    const float4* p1 = (const float4*)(cb + (size_t)c1 * D);
    const float4* p2 = (const float4*)(cb + (size_t)c2 * D);
    float s0 = 0.f, s1 = 0.f, s2 = 0.f;
#pragma unroll
    for (int i = 0; i < 4; ++i) {
        float4 zv = zr[lane + i * 32];
        float4 a = p0[lane + i * 32], b = p1[lane + i * 32], c = p2[lane + i * 32];
        s0 += zv.x * a.x + zv.y * a.y + zv.z * a.z + zv.w * a.w;
        s1 += zv.x * b.x + zv.y * b.y + zv.z * b.z + zv.w * b.w;
        s2 += zv.x * c.x + zv.y * c.y + zv.z * c.z + zv.w * c.w;
    }
#pragma unroll
    for (int off = 16; off; off >>= 1) {
        s0 += __shfl_down_sync(0xffffffffu, s0, off);
        s1 += __shfl_down_sync(0xffffffffu, s1, off);
        s2 += __shfl_down_sync(0xffffffffu, s2, off);
    }
    if (lane == 0) {
        float zsq = g_zsq[warp];
        float d0 = fmaxf(zsq + g_csq[c0] - 2.f * s0, 0.f);
        float d1 = fmaxf(zsq + g_csq[c1] - 2.f * s1, 0.f);
        float d2 = fmaxf(zsq + g_csq[c2] - 2.f * s2, 0.f);
        float bd = d0; int bi = c0;
        if (d1 < bd || (d1 == bd && c1 < bi)) { bd = d1; bi = c1; }
        if (d2 < bd || (d2 == bd && c2 < bi)) { bd = d2; bi = c2; }
        g_idx[warp]  = bi;
        g_dmin[warp] = sqrtf(bd);
    }
}

// ---------------- scalar loss reduction ----------------
__global__ void loss_kernel(int N) {
    __shared__ float sd[1024], sh[1024];
    int t = threadIdx.x;
    float a = 0.f, b = 0.f;
    for (int i = t; i < N; i += 1024) { a += g_dmin[i]; b += g_H[i]; }
    sd[t] = a; sh[t] = b;
    __syncthreads();
    for (int off = 512; off; off >>= 1) {
        if (t < off) { sd[t] += sd[t + off]; sh[t] += sh[t + off]; }
        __syncthreads();
    }
    if (t == 0) g_loss = sd[0] / (float)N + 0.1f * sh[0] / (float)N;
}

// ---------------- outputs ----------------
__global__ void out_kernel(const float* __restrict__ cb, const float* __restrict__ yb,
                           const float* __restrict__ et, float* __restrict__ out, int N) {
    int warp = (blockIdx.x * blockDim.x + threadIdx.x) >> 5;
    int lane = threadIdx.x & 31;
    if (warp >= N) return;
    int idx = g_idx[warp];
    const float4* crow = (const float4*)(cb + (size_t)idx * D);
    const float4* yrow = (const float4*)(yb + (size_t)warp * D);
    float4*       qrow = (float4*)(out + (size_t)warp * D);
    float acc = 0.f;
#pragma unroll
    for (int i = 0; i < 4; ++i) {
        float4 cv = crow[lane + i * 32];
        float4 yv = yrow[lane + i * 32];
        qrow[lane + i * 32] = cv;
        float dx = cv.x - yv.x, dy = cv.y - yv.y, dz = cv.z - yv.z, dw = cv.w - yv.w;
        acc += dx * dx + dy * dy + dz * dz + dw * dw;
    }
#pragma unroll
    for (int off = 16; off; off >>= 1) acc += __shfl_down_sync(0xffffffffu, acc, off);
    if (lane == 0) {
        float dev = sqrtf(acc);
        out[(size_t)N * D + warp]     = g_loss;
        out[(size_t)N * D + N + warp] = et[warp] + (dev > 0.01f ? 1.0f : 0.0f);
    }
}

extern "C" void kernel_launch(void* const* d_in, const int* in_sizes, int n_in,
                              void* d_out, int out_size) {
    const float* z  = (const float*)d_in[0];
    const float* yb = (const float*)d_in[1];
    const float* et = (const float*)d_in[2];
    const float* cb = (const float*)d_in[3];
    int N = in_sizes[0] / D;
    int K = in_sizes[3] / D;
    float* out = (float*)d_out;

    cudaFuncSetAttribute(gemm_kernel, cudaFuncAttributeMaxDynamicSharedMemorySize, SMEM_SZ);

    split_kernel<<<(N + 7) / 8, 256>>>(z, N, 0);
    split_kernel<<<(K + 7) / 8, 256>>>(cb, K, 1);
    gemm_kernel<<<N / MT, 256, SMEM_SZ>>>();
    fixup_kernel<<<(N + 7) / 8, 256>>>(z, cb, N);
    loss_kernel<<<1, 1024>>>(N);
    out_kernel<<<(N + 7) / 8, 256>>>(cb, yb, et, out, N);
}

// round 5
// speedup vs baseline: 6.2302x; 1.4940x over previous
#include <cuda_runtime.h>
#include <cuda_bf16.h>
#include <math.h>
#include <stdint.h>

#define D    512
#define NTOK 32768
#define KCB  8192
#define MT   128              // rows per CTA
#define NT   128              // codes per n-iter
#define KC   64               // k per chunk
#define NITER ((KCB / NT) * (D / KC))   // 64 * 8 = 512
#define A_BYTES (MT * D * 2)            // 131072
#define B_STAGE (NT * KC * 2)           // 16384 (hi only)
#define NSTAGE 4
#define SMEM_SZ (A_BYTES + NSTAGE * B_STAGE) // 196608

// ---------------- device globals ----------------
__device__ __nv_bfloat16 g_zh[(size_t)NTOK * D];
__device__ __nv_bfloat16 g_ch[(size_t)KCB * D];
__device__ float g_zsq[NTOK];
__device__ float g_csq[KCB];
__device__ float g_dmin[NTOK];
__device__ float g_H[NTOK];
__device__ int   g_c0[NTOK], g_c1[NTOK], g_c2[NTOK];
__device__ int   g_idx[NTOK];
__device__ float g_loss;

// ---------------- helpers ----------------
__device__ __forceinline__ uint32_t smem_u32(const void* p) {
    uint32_t a;
    asm("{ .reg .u64 t; cvta.to.shared.u64 t, %1; cvt.u32.u64 %0, t; }" : "=r"(a) : "l"(p));
    return a;
}
__device__ __forceinline__ void cp16(uint32_t s, const void* g) {
    asm volatile("cp.async.cg.shared.global [%0], [%1], 16;" :: "r"(s), "l"(g));
}
#define CP_COMMIT()  asm volatile("cp.async.commit_group;" ::: "memory")
#define CP_WAIT(n)   asm volatile("cp.async.wait_group %0;" :: "n"(n) : "memory")

__device__ __forceinline__ void ldsm4(uint32_t& r0, uint32_t& r1, uint32_t& r2, uint32_t& r3, uint32_t a) {
    asm volatile("ldmatrix.sync.aligned.m8n8.x4.shared.b16 {%0,%1,%2,%3}, [%4];"
                 : "=r"(r0), "=r"(r1), "=r"(r2), "=r"(r3) : "r"(a));
}
__device__ __forceinline__ void mma16816(float* c, uint32_t a0, uint32_t a1, uint32_t a2, uint32_t a3,
                                         uint32_t b0, uint32_t b1) {
    asm volatile("mma.sync.aligned.m16n8k16.row.col.f32.bf16.bf16.f32 "
                 "{%0,%1,%2,%3},{%4,%5,%6,%7},{%8,%9},{%0,%1,%2,%3};"
                 : "+f"(c[0]), "+f"(c[1]), "+f"(c[2]), "+f"(c[3])
                 : "r"(a0), "r"(a1), "r"(a2), "r"(a3), "r"(b0), "r"(b1));
}
__device__ __forceinline__ float sqrt_apx(float x) {
    float r; asm("sqrt.approx.f32 %0, %1;" : "=f"(r) : "f"(x)); return r;
}

// ---------------- split: fp32 -> bf16 hi + row sumsq ----------------
__global__ void split_kernel(const float* __restrict__ src, int rows, int which) {
    int warp = (blockIdx.x * blockDim.x + threadIdx.x) >> 5;
    int lane = threadIdx.x & 31;
    if (warp >= rows) return;
    const float4* p = (const float4*)(src + (size_t)warp * D);
    __nv_bfloat16* dst = which ? g_ch : g_zh;
    float acc = 0.f;
#pragma unroll
    for (int i = 0; i < 4; ++i) {
        float4 v = p[lane + i * 32];
        acc += v.x * v.x + v.y * v.y + v.z * v.z + v.w * v.w;
        float xs[4] = {v.x, v.y, v.z, v.w};
        size_t base = (size_t)warp * D + (lane + i * 32) * 4;
#pragma unroll
        for (int j = 0; j < 4; ++j) dst[base + j] = __float2bfloat16(xs[j]);
    }
#pragma unroll
    for (int off = 16; off; off >>= 1) acc += __shfl_down_sync(0xffffffffu, acc, off);
    if (lane == 0) { if (which) g_csq[warp] = acc; else g_zsq[warp] = acc; }
}

// ---------------- B chunk loader (hi only, 16KB) ----------------
__device__ __forceinline__ void load_b(uint32_t sb, int iter, int tid) {
    int nt = iter >> 3, kc = iter & 7;
    uint32_t st = sb + A_BYTES + (uint32_t)(iter & (NSTAGE - 1)) * B_STAGE;
    const __nv_bfloat16* bh = g_ch + (size_t)(nt * NT) * D + kc * KC;
#pragma unroll
    for (int i = 0; i < 4; ++i) {
        int q = tid + i * 256;
        int r = q >> 3, c16 = q & 7;
        uint32_t off = (uint32_t)(r * 128 + ((c16 * 16) ^ ((r & 7) << 4)));
        cp16(st + off, bh + (size_t)r * D + c16 * 8);
    }
}

// ---------------- main HMMA GEMM + fused epilogue ----------------
__global__ void __launch_bounds__(256, 1) gemm_kernel() {
    extern __shared__ __align__(1024) char sm[];
    uint32_t sb = smem_u32(sm);
    int tid = threadIdx.x, lane = tid & 31, wid = tid >> 5;
    int wm = wid & 3, wn = wid >> 2;          // warp grid 4(M) x 2(N); warp tile 32x64
    int n0 = blockIdx.x * MT;

    // ---- load A (z hi, 128x512 bf16) resident, swizzled chunks of [128][64]
    {
        const __nv_bfloat16* zb = g_zh + (size_t)n0 * D;
#pragma unroll
        for (int i = 0; i < 32; ++i) {
            int q = tid + i * 256;
            int kc = q >> 10, u = q & 1023, r = u >> 3, c16 = u & 7;
            uint32_t so = sb + (uint32_t)(kc * 16384 + r * 128 + ((c16 * 16) ^ ((r & 7) << 4)));
            cp16(so, zb + (size_t)r * D + kc * KC + c16 * 8);
        }
    }
    load_b(sb, 0, tid); CP_COMMIT();
    load_b(sb, 1, tid); CP_COMMIT();
    load_b(sb, 2, tid); CP_COMMIT();

    // per-thread per-row state: s = mt*2 + h  (4 rows per thread)
    float m1[4], ss[4], tt[4], zs[4];
    float tv[4][3]; int ti[4][3];
#pragma unroll
    for (int s = 0; s < 4; ++s) {
        m1[s] = 60.f; ss[s] = 0.f; tt[s] = 0.f;
        tv[s][0] = tv[s][1] = tv[s][2] = 1e30f;
        ti[s][0] = ti[s][1] = ti[s][2] = 0;
        int row = n0 + wm * 32 + (s >> 1) * 16 + (lane >> 2) + (s & 1) * 8;
        zs[s] = g_zsq[row];
    }

    float acc[2][8][4];
    int laneA_r[2], laneB_r[4];
#pragma unroll
    for (int mt = 0; mt < 2; ++mt)
        laneA_r[mt] = wm * 32 + mt * 16 + (lane & 7) + ((lane >> 3) & 1) * 8;
#pragma unroll
    for (int p = 0; p < 4; ++p)
        laneB_r[p] = wn * 64 + (p * 2 + ((lane >> 4) & 1)) * 8 + (lane & 7);
    int byteA = ((lane >> 4) & 1) * 16;
    int byteB = ((lane >> 3) & 1) * 16;

    for (int it = 0; it < NITER; ++it) {
        CP_WAIT(2);
        __syncthreads();
        if (it + 3 < NITER) { load_b(sb, it + 3, tid); CP_COMMIT(); }

        int kc = it & 7;
        uint32_t abase = sb + kc * 16384;
        uint32_t bbase = sb + A_BYTES + (uint32_t)(it & (NSTAGE - 1)) * B_STAGE;

        if (kc == 0) {
#pragma unroll
            for (int mt = 0; mt < 2; ++mt)
#pragma unroll
                for (int n = 0; n < 8; ++n)
#pragma unroll
                    for (int q = 0; q < 4; ++q) acc[mt][n][q] = 0.f;
        }

#pragma unroll
        for (int j = 0; j < 4; ++j) {
            uint32_t a[2][4];
#pragma unroll
            for (int mt = 0; mt < 2; ++mt) {
                int r = laneA_r[mt];
                uint32_t ad = abase + (uint32_t)(r * 128 + ((j * 32 + byteA) ^ ((r & 7) << 4)));
                ldsm4(a[mt][0], a[mt][1], a[mt][2], a[mt][3], ad);
            }
            uint32_t bh[8][2];
#pragma unroll
            for (int p = 0; p < 4; ++p) {
                int r = laneB_r[p];
                uint32_t off = (uint32_t)(r * 128 + ((j * 32 + byteB) ^ ((r & 7) << 4)));
                ldsm4(bh[2 * p][0], bh[2 * p][1], bh[2 * p + 1][0], bh[2 * p + 1][1], bbase + off);
            }
#pragma unroll
            for (int mt = 0; mt < 2; ++mt)
#pragma unroll
                for (int n = 0; n < 8; ++n)
                    mma16816(acc[mt][n], a[mt][0], a[mt][1], a[mt][2], a[mt][3], bh[n][0], bh[n][1]);
        }

        if (kc == 7) {                        // fused epilogue for this 128-code tile
            int nt = it >> 3;
            int colbase = nt * 128 + wn * 64 + (lane & 3) * 2;
            float csv[16];
#pragma unroll
            for (int n = 0; n < 8; ++n) {
                csv[2 * n]     = __ldg(g_csq + colbase + n * 8);
                csv[2 * n + 1] = __ldg(g_csq + colbase + n * 8 + 1);
            }
#pragma unroll
            for (int mt = 0; mt < 2; ++mt)
#pragma unroll
                for (int n = 0; n < 8; ++n)
#pragma unroll
                    for (int h = 0; h < 2; ++h)
#pragma unroll
                        for (int q = 0; q < 2; ++q) {
                            int s = mt * 2 + h;
                            float dot = acc[mt][n][h * 2 + q];
                            int code = colbase + n * 8 + q;
                            float d2 = fmaf(-2.f, dot, zs[s] + csv[2 * n + q]);
                            d2 = fmaxf(d2, 1e-6f);
                            float d = sqrt_apx(d2);        // MUFU
                            if (d2 < tv[s][2]) {           // top-3 (rare path)
                                if (d2 < tv[s][1]) {
                                    tv[s][2] = tv[s][1]; ti[s][2] = ti[s][1];
                                    if (d2 < tv[s][0]) {
                                        tv[s][1] = tv[s][0]; ti[s][1] = ti[s][0];
                                        tv[s][0] = d2; ti[s][0] = code;
                                    } else { tv[s][1] = d2; ti[s][1] = code; }
                                } else { tv[s][2] = d2; ti[s][2] = code; }
                            }
                            bool nm = d < m1[s];
                            float e = __expf(nm ? (d - m1[s]) : (m1[s] - d));  // MUFU ex2
                            if (nm) {
                                ss[s] = fmaf(ss[s], e, 1.f);
                                tt[s] = fmaf(tt[s], e, d);
                                m1[s] = d;
                            } else {
                                ss[s] += e;
                                tt[s] = fmaf(e, d, tt[s]);
                            }
                        }
        }
    }

    // ---- merge 8 partials per row via smem (reuse B area)
    __syncthreads();
    float* msm = (float*)(sm + A_BYTES);
    int*   mim = (int*)msm;
#pragma unroll
    for (int s = 0; s < 4; ++s) {
        int row_local = wm * 32 + (s >> 1) * 16 + (lane >> 2) + (s & 1) * 8;
        int base = (row_local * 8 + wn * 4 + (lane & 3)) * 9;
        msm[base + 0] = m1[s]; msm[base + 1] = ss[s]; msm[base + 2] = tt[s];
        msm[base + 3] = tv[s][0]; msm[base + 4] = tv[s][1]; msm[base + 5] = tv[s][2];
        mim[base + 6] = ti[s][0]; mim[base + 7] = ti[s][1]; mim[base + 8] = ti[s][2];
    }
    __syncthreads();
    if (tid < 128) {
        int row = tid;
        float M = 1e30f;
#pragma unroll
        for (int j = 0; j < 8; ++j) M = fminf(M, msm[(row * 8 + j) * 9]);
        float S = 0.f, T = 0.f;
        float bv0 = 1e30f, bv1 = 1e30f, bv2 = 1e30f;
        int bi0 = 0, bi1 = 0, bi2 = 0;
#pragma unroll
        for (int j = 0; j < 8; ++j) {
            int base = (row * 8 + j) * 9;
            float fct = __expf(M - msm[base + 0]);
            S = fmaf(msm[base + 1], fct, S);
            T = fmaf(msm[base + 2], fct, T);
#pragma unroll
            for (int k = 0; k < 3; ++k) {
                float v = msm[base + 3 + k];
                int   ix = mim[base + 6 + k];
                if (v < bv2) {
                    if (v < bv1) {
                        bv2 = bv1; bi2 = bi1;
                        if (v < bv0) { bv1 = bv0; bi1 = bi0; bv0 = v; bi0 = ix; }
                        else         { bv1 = v;  bi1 = ix; }
                    } else { bv2 = v; bi2 = ix; }
                }
            }
        }
        int grow = n0 + row;
        g_H[grow]  = __logf(S) - M + T / S;
        g_c0[grow] = bi0; g_c1[grow] = bi1; g_c2[grow] = bi2;
    }
}

// ---------------- exact fp32 rescore of top-3 candidates ----------------
__global__ void fixup_kernel(const float* __restrict__ z, const float* __restrict__ cb, int N) {
    int warp = (blockIdx.x * blockDim.x + threadIdx.x) >> 5;
    int lane = threadIdx.x & 31;
    if (warp >= N) return;
    int c0 = g_c0[warp], c1 = g_c1[warp], c2 = g_c2[warp];
    const float4* zr = (const float4*)(z + (size_t)warp * D);
    const float4* p0 = (const float4*)(cb + (size_t)c0 * D);
    const float4* p1 = (const float4*)(cb + (size_t)c1 * D);
    const float4* p2 = (const float4*)(cb + (size_t)c2 * D);
    float s0 = 0.f, s1 = 0.f, s2 = 0.f;
#pragma unroll
    for (int i = 0; i < 4; ++i) {
        float4 zv = zr[lane + i * 32];
        float4 a = p0[lane + i * 32], b = p1[lane + i * 32], c = p2[lane + i * 32];
        s0 += zv.x * a.x + zv.y * a.y + zv.z * a.z + zv.w * a.w;
        s1 += zv.x * b.x + zv.y * b.y + zv.z * b.z + zv.w * b.w;
        s2 += zv.x * c.x + zv.y * c.y + zv.z * c.z + zv.w * c.w;
    }
#pragma unroll
    for (int off = 16; off; off >>= 1) {
        s0 += __shfl_down_sync(0xffffffffu, s0, off);
        s1 += __shfl_down_sync(0xffffffffu, s1, off);
        s2 += __shfl_down_sync(0xffffffffu, s2, off);
    }
    if (lane == 0) {
        float zsq = g_zsq[warp];
        float d0 = fmaxf(zsq + g_csq[c0] - 2.f * s0, 0.f);
        float d1 = fmaxf(zsq + g_csq[c1] - 2.f * s1, 0.f);
        float d2 = fmaxf(zsq + g_csq[c2] - 2.f * s2, 0.f);
        float bd = d0; int bi = c0;
        if (d1 < bd || (d1 == bd && c1 < bi)) { bd = d1; bi = c1; }
        if (d2 < bd || (d2 == bd && c2 < bi)) { bd = d2; bi = c2; }
        g_idx[warp]  = bi;
        g_dmin[warp] = sqrtf(bd);
    }
}

// ---------------- scalar loss reduction ----------------
__global__ void loss_kernel(int N) {
    __shared__ float sd[1024], sh[1024];
    int t = threadIdx.x;
    float a = 0.f, b = 0.f;
    for (int i = t; i < N; i += 1024) { a += g_dmin[i]; b += g_H[i]; }
    sd[t] = a; sh[t] = b;
    __syncthreads();
    for (int off = 512; off; off >>= 1) {
        if (t < off) { sd[t] += sd[t + off]; sh[t] += sh[t + off]; }
        __syncthreads();
    }
    if (t == 0) g_loss = sd[0] / (float)N + 0.1f * sh[0] / (float)N;
}

// ---------------- outputs ----------------
__global__ void out_kernel(const float* __restrict__ cb, const float* __restrict__ yb,
                           const float* __restrict__ et, float* __restrict__ out, int N) {
    int warp = (blockIdx.x * blockDim.x + threadIdx.x) >> 5;
    int lane = threadIdx.x & 31;
    if (warp >= N) return;
    int idx = g_idx[warp];
    const float4* crow = (const float4*)(cb + (size_t)idx * D);
    const float4* yrow = (const float4*)(yb + (size_t)warp * D);
    float4*       qrow = (float4*)(out + (size_t)warp * D);
    float acc = 0.f;
#pragma unroll
    for (int i = 0; i < 4; ++i) {
        float4 cv = crow[lane + i * 32];
        float4 yv = yrow[lane + i * 32];
        qrow[lane + i * 32] = cv;
        float dx = cv.x - yv.x, dy = cv.y - yv.y, dz = cv.z - yv.z, dw = cv.w - yv.w;
        acc += dx * dx + dy * dy + dz * dz + dw * dw;
    }
#pragma unroll
    for (int off = 16; off; off >>= 1) acc += __shfl_down_sync(0xffffffffu, acc, off);
    if (lane == 0) {
        float dev = sqrtf(acc);
        out[(size_t)N * D + warp]     = g_loss;
        out[(size_t)N * D + N + warp] = et[warp] + (dev > 0.01f ? 1.0f : 0.0f);
    }
}

extern "C" void kernel_launch(void* const* d_in, const int* in_sizes, int n_in,
                              void* d_out, int out_size) {
    const float* z  = (const float*)d_in[0];
    const float* yb = (const float*)d_in[1];
    const float* et = (const float*)d_in[2];
    const float* cb = (const float*)d_in[3];
    int N = in_sizes[0] / D;
    int K = in_sizes[3] / D;
    float* out = (float*)d_out;

    cudaFuncSetAttribute(gemm_kernel, cudaFuncAttributeMaxDynamicSharedMemorySize, SMEM_SZ);

    split_kernel<<<(N + 7) / 8, 256>>>(z, N, 0);
    split_kernel<<<(K + 7) / 8, 256>>>(cb, K, 1);
    gemm_kernel<<<N / MT, 256, SMEM_SZ>>>();
    fixup_kernel<<<(N + 7) / 8, 256>>>(z, cb, N);
    loss_kernel<<<1, 1024>>>(N);
    out_kernel<<<(N + 7) / 8, 256>>>(cb, yb, et, out, N);
}

// round 6
// speedup vs baseline: 6.5830x; 1.0566x over previous
#include <cuda_runtime.h>
#include <cuda_bf16.h>
#include <math.h>
#include <stdint.h>

#define D    512
#define NTOK 32768
#define KCB  8192
#define MT   128              // rows per CTA
#define NT   128              // codes per n-iter
#define KC   64               // k per chunk
#define KQ   4                // codebook quarters (work-split)
#define KQ_CODES (KCB / KQ)   // 2048
#define NITER ((KQ_CODES / NT) * (D / KC))   // 16 * 8 = 128
#define A_BYTES (MT * D * 2)            // 131072
#define B_STAGE (NT * KC * 2)           // 16384
#define NSTAGE 4
#define SMEM_SZ (A_BYTES + NSTAGE * B_STAGE) // 196608

// ---------------- device globals ----------------
__device__ __nv_bfloat16 g_zh[(size_t)NTOK * D];
__device__ __nv_bfloat16 g_ch[(size_t)KCB * D];
__device__ float g_zsq[NTOK];
__device__ float g_csq[KCB];
__device__ float g_dmin[NTOK];
__device__ float g_H[NTOK];
__device__ int   g_idx[NTOK];
__device__ float g_loss;
// per (kq, row) partials
__device__ float g_pm[KQ * NTOK], g_ps[KQ * NTOK], g_pt[KQ * NTOK];
__device__ float g_pv0[KQ * NTOK], g_pv1[KQ * NTOK], g_pv2[KQ * NTOK];
__device__ int   g_pi0[KQ * NTOK], g_pi1[KQ * NTOK], g_pi2[KQ * NTOK];

// ---------------- helpers ----------------
__device__ __forceinline__ uint32_t smem_u32(const void* p) {
    uint32_t a;
    asm("{ .reg .u64 t; cvta.to.shared.u64 t, %1; cvt.u32.u64 %0, t; }" : "=r"(a) : "l"(p));
    return a;
}
__device__ __forceinline__ void cp16(uint32_t s, const void* g) {
    asm volatile("cp.async.cg.shared.global [%0], [%1], 16;" :: "r"(s), "l"(g));
}
#define CP_COMMIT()  asm volatile("cp.async.commit_group;" ::: "memory")
#define CP_WAIT(n)   asm volatile("cp.async.wait_group %0;" :: "n"(n) : "memory")

__device__ __forceinline__ void ldsm4(uint32_t& r0, uint32_t& r1, uint32_t& r2, uint32_t& r3, uint32_t a) {
    asm volatile("ldmatrix.sync.aligned.m8n8.x4.shared.b16 {%0,%1,%2,%3}, [%4];"
                 : "=r"(r0), "=r"(r1), "=r"(r2), "=r"(r3) : "r"(a));
}
__device__ __forceinline__ void mma16816(float* c, uint32_t a0, uint32_t a1, uint32_t a2, uint32_t a3,
                                         uint32_t b0, uint32_t b1) {
    asm volatile("mma.sync.aligned.m16n8k16.row.col.f32.bf16.bf16.f32 "
                 "{%0,%1,%2,%3},{%4,%5,%6,%7},{%8,%9},{%0,%1,%2,%3};"
                 : "+f"(c[0]), "+f"(c[1]), "+f"(c[2]), "+f"(c[3])
                 : "r"(a0), "r"(a1), "r"(a2), "r"(a3), "r"(b0), "r"(b1));
}
__device__ __forceinline__ float sqrt_apx(float x) {
    float r; asm("sqrt.approx.f32 %0, %1;" : "=f"(r) : "f"(x)); return r;
}

// ---------------- fused split: z rows then codebook rows ----------------
__global__ void split_kernel(const float* __restrict__ z, const float* __restrict__ cb,
                             int N, int K) {
    int w = (blockIdx.x * blockDim.x + threadIdx.x) >> 5;
    int lane = threadIdx.x & 31;
    if (w >= N + K) return;
    int which = (w >= N);
    int row = which ? (w - N) : w;
    const float* src = which ? cb : z;
    __nv_bfloat16* dst = which ? g_ch : g_zh;
    const float4* p = (const float4*)(src + (size_t)row * D);
    float acc = 0.f;
#pragma unroll
    for (int i = 0; i < 4; ++i) {
        float4 v = p[lane + i * 32];
        acc += v.x * v.x + v.y * v.y + v.z * v.z + v.w * v.w;
        float xs[4] = {v.x, v.y, v.z, v.w};
        size_t base = (size_t)row * D + (lane + i * 32) * 4;
#pragma unroll
        for (int j = 0; j < 4; ++j) dst[base + j] = __float2bfloat16(xs[j]);
    }
#pragma unroll
    for (int off = 16; off; off >>= 1) acc += __shfl_down_sync(0xffffffffu, acc, off);
    if (lane == 0) { if (which) g_csq[row] = acc; else g_zsq[row] = acc; }
}

// ---------------- B chunk loader ----------------
__device__ __forceinline__ void load_b(uint32_t sb, int iter, int tid, int code_base) {
    int nt = iter >> 3, kc = iter & 7;
    uint32_t st = sb + A_BYTES + (uint32_t)(iter & (NSTAGE - 1)) * B_STAGE;
    const __nv_bfloat16* bh = g_ch + (size_t)(code_base + nt * NT) * D + kc * KC;
#pragma unroll
    for (int i = 0; i < 4; ++i) {
        int q = tid + i * 256;
        int r = q >> 3, c16 = q & 7;
        uint32_t off = (uint32_t)(r * 128 + ((c16 * 16) ^ ((r & 7) << 4)));
        cp16(st + off, bh + (size_t)r * D + c16 * 8);
    }
}

// ---------------- main HMMA GEMM + fused epilogue (one K-quarter) ----------------
__global__ void __launch_bounds__(256, 1) gemm_kernel() {
    extern __shared__ __align__(1024) char sm[];
    uint32_t sb = smem_u32(sm);
    int tid = threadIdx.x, lane = tid & 31, wid = tid >> 5;
    int wm = wid & 3, wn = wid >> 2;          // warp grid 4(M) x 2(N); warp tile 32x64
    int mt = blockIdx.x & 255;
    int kq = blockIdx.x >> 8;
    int n0 = mt * MT;
    int code_base = kq * KQ_CODES;

    // ---- load A (z hi, 128x512 bf16) resident, swizzled chunks of [128][64]
    {
        const __nv_bfloat16* zb = g_zh + (size_t)n0 * D;
#pragma unroll
        for (int i = 0; i < 32; ++i) {
            int q = tid + i * 256;
            int kc = q >> 10, u = q & 1023, r = u >> 3, c16 = u & 7;
            uint32_t so = sb + (uint32_t)(kc * 16384 + r * 128 + ((c16 * 16) ^ ((r & 7) << 4)));
            cp16(so, zb + (size_t)r * D + kc * KC + c16 * 8);
        }
    }
    load_b(sb, 0, tid, code_base); CP_COMMIT();
    load_b(sb, 1, tid, code_base); CP_COMMIT();
    load_b(sb, 2, tid, code_base); CP_COMMIT();

    float m1[4], ss[4], tt[4], zs[4];
    float tv[4][3]; int ti[4][3];
#pragma unroll
    for (int s = 0; s < 4; ++s) {
        m1[s] = 60.f; ss[s] = 0.f; tt[s] = 0.f;
        tv[s][0] = tv[s][1] = tv[s][2] = 1e30f;
        ti[s][0] = ti[s][1] = ti[s][2] = 0;
        int row = n0 + wm * 32 + (s >> 1) * 16 + (lane >> 2) + (s & 1) * 8;
        zs[s] = g_zsq[row];
    }

    float acc[2][8][4];
    int laneA_r[2], laneB_r[4];
#pragma unroll
    for (int m = 0; m < 2; ++m)
        laneA_r[m] = wm * 32 + m * 16 + (lane & 7) + ((lane >> 3) & 1) * 8;
#pragma unroll
    for (int p = 0; p < 4; ++p)
        laneB_r[p] = wn * 64 + (p * 2 + ((lane >> 4) & 1)) * 8 + (lane & 7);
    int byteA = ((lane >> 4) & 1) * 16;
    int byteB = ((lane >> 3) & 1) * 16;

    for (int it = 0; it < NITER; ++it) {
        CP_WAIT(2);
        __syncthreads();
        if (it + 3 < NITER) { load_b(sb, it + 3, tid, code_base); CP_COMMIT(); }

        int kc = it & 7;
        uint32_t abase = sb + kc * 16384;
        uint32_t bbase = sb + A_BYTES + (uint32_t)(it & (NSTAGE - 1)) * B_STAGE;

        if (kc == 0) {
#pragma unroll
            for (int m = 0; m < 2; ++m)
#pragma unroll
                for (int n = 0; n < 8; ++n)
#pragma unroll
                    for (int q = 0; q < 4; ++q) acc[m][n][q] = 0.f;
        }

#pragma unroll
        for (int j = 0; j < 4; ++j) {
            uint32_t a[2][4];
#pragma unroll
            for (int m = 0; m < 2; ++m) {
                int r = laneA_r[m];
                uint32_t ad = abase + (uint32_t)(r * 128 + ((j * 32 + byteA) ^ ((r & 7) << 4)));
                ldsm4(a[m][0], a[m][1], a[m][2], a[m][3], ad);
            }
            uint32_t bh[8][2];
#pragma unroll
            for (int p = 0; p < 4; ++p) {
                int r = laneB_r[p];
                uint32_t off = (uint32_t)(r * 128 + ((j * 32 + byteB) ^ ((r & 7) << 4)));
                ldsm4(bh[2 * p][0], bh[2 * p][1], bh[2 * p + 1][0], bh[2 * p + 1][1], bbase + off);
            }
#pragma unroll
            for (int m = 0; m < 2; ++m)
#pragma unroll
                for (int n = 0; n < 8; ++n)
                    mma16816(acc[m][n], a[m][0], a[m][1], a[m][2], a[m][3], bh[n][0], bh[n][1]);
        }

        if (kc == 7) {                        // fused epilogue for this 128-code tile
            int nt = it >> 3;
            int colbase = code_base + nt * NT + wn * 64 + (lane & 3) * 2;
            float csv[16];
#pragma unroll
            for (int n = 0; n < 8; ++n) {
                csv[2 * n]     = __ldg(g_csq + colbase + n * 8);
                csv[2 * n + 1] = __ldg(g_csq + colbase + n * 8 + 1);
            }
#pragma unroll
            for (int m = 0; m < 2; ++m)
#pragma unroll
                for (int n = 0; n < 8; ++n)
#pragma unroll
                    for (int h = 0; h < 2; ++h)
#pragma unroll
                        for (int q = 0; q < 2; ++q) {
                            int s = m * 2 + h;
                            float dot = acc[m][n][h * 2 + q];
                            int code = colbase + n * 8 + q;
                            float d2 = fmaf(-2.f, dot, zs[s] + csv[2 * n + q]);
                            d2 = fmaxf(d2, 1e-6f);
                            float d = sqrt_apx(d2);
                            if (d2 < tv[s][2]) {
                                if (d2 < tv[s][1]) {
                                    tv[s][2] = tv[s][1]; ti[s][2] = ti[s][1];
                                    if (d2 < tv[s][0]) {
                                        tv[s][1] = tv[s][0]; ti[s][1] = ti[s][0];
                                        tv[s][0] = d2; ti[s][0] = code;
                                    } else { tv[s][1] = d2; ti[s][1] = code; }
                                } else { tv[s][2] = d2; ti[s][2] = code; }
                            }
                            bool nm = d < m1[s];
                            float e = __expf(nm ? (d - m1[s]) : (m1[s] - d));
                            if (nm) {
                                ss[s] = fmaf(ss[s], e, 1.f);
                                tt[s] = fmaf(tt[s], e, d);
                                m1[s] = d;
                            } else {
                                ss[s] += e;
                                tt[s] = fmaf(e, d, tt[s]);
                            }
                        }
        }
    }

    // ---- merge 8 warp-partials per row via smem, write one partial per (kq,row)
    __syncthreads();
    float* msm = (float*)(sm + A_BYTES);
    int*   mim = (int*)msm;
#pragma unroll
    for (int s = 0; s < 4; ++s) {
        int row_local = wm * 32 + (s >> 1) * 16 + (lane >> 2) + (s & 1) * 8;
        int base = (row_local * 8 + wn * 4 + (lane & 3)) * 9;
        msm[base + 0] = m1[s]; msm[base + 1] = ss[s]; msm[base + 2] = tt[s];
        msm[base + 3] = tv[s][0]; msm[base + 4] = tv[s][1]; msm[base + 5] = tv[s][2];
        mim[base + 6] = ti[s][0]; mim[base + 7] = ti[s][1]; mim[base + 8] = ti[s][2];
    }
    __syncthreads();
    if (tid < 128) {
        int row = tid;
        float M = 1e30f;
#pragma unroll
        for (int j = 0; j < 8; ++j) M = fminf(M, msm[(row * 8 + j) * 9]);
        float S = 0.f, T = 0.f;
        float bv0 = 1e30f, bv1 = 1e30f, bv2 = 1e30f;
        int bi0 = 0, bi1 = 0, bi2 = 0;
#pragma unroll
        for (int j = 0; j < 8; ++j) {
            int base = (row * 8 + j) * 9;
            float fct = __expf(M - msm[base + 0]);
            S = fmaf(msm[base + 1], fct, S);
            T = fmaf(msm[base + 2], fct, T);
#pragma unroll
            for (int k = 0; k < 3; ++k) {
                float v = msm[base + 3 + k];
                int   ix = mim[base + 6 + k];
                if (v < bv2) {
                    if (v < bv1) {
                        bv2 = bv1; bi2 = bi1;
                        if (v < bv0) { bv1 = bv0; bi1 = bi0; bv0 = v; bi0 = ix; }
                        else         { bv1 = v;  bi1 = ix; }
                    } else { bv2 = v; bi2 = ix; }
                }
            }
        }
        int gp = kq * NTOK + n0 + row;
        g_pm[gp] = M; g_ps[gp] = S; g_pt[gp] = T;
        g_pv0[gp] = bv0; g_pv1[gp] = bv1; g_pv2[gp] = bv2;
        g_pi0[gp] = bi0; g_pi1[gp] = bi1; g_pi2[gp] = bi2;
    }
}

// ---------------- merge 4 K-quarter partials + exact fp32 rescore ----------------
__global__ void mergefix_kernel(const float* __restrict__ z, const float* __restrict__ cb, int N) {
    int warp = (blockIdx.x * blockDim.x + threadIdx.x) >> 5;
    int lane = threadIdx.x & 31;
    if (warp >= N) return;

    // all lanes do the identical merge (broadcast loads)
    float M = 1e30f;
#pragma unroll
    for (int j = 0; j < KQ; ++j) M = fminf(M, g_pm[j * NTOK + warp]);
    float S = 0.f, T = 0.f;
    float bv0 = 1e30f, bv1 = 1e30f, bv2 = 1e30f;
    int bi0 = 0, bi1 = 0, bi2 = 0;
#pragma unroll
    for (int j = 0; j < KQ; ++j) {
        int gp = j * NTOK + warp;
        float fct = __expf(M - g_pm[gp]);
        S = fmaf(g_ps[gp], fct, S);
        T = fmaf(g_pt[gp], fct, T);
        float vs[3] = {g_pv0[gp], g_pv1[gp], g_pv2[gp]};
        int   is[3] = {g_pi0[gp], g_pi1[gp], g_pi2[gp]};
#pragma unroll
        for (int k = 0; k < 3; ++k) {
            float v = vs[k]; int ix = is[k];
            if (v < bv2) {
                if (v < bv1) {
                    bv2 = bv1; bi2 = bi1;
                    if (v < bv0) { bv1 = bv0; bi1 = bi0; bv0 = v; bi0 = ix; }
                    else         { bv1 = v;  bi1 = ix; }
                } else { bv2 = v; bi2 = ix; }
            }
        }
    }

    // exact fp32 rescore of the 3 merged candidates
    const float4* zr = (const float4*)(z + (size_t)warp * D);
    const float4* p0 = (const float4*)(cb + (size_t)bi0 * D);
    const float4* p1 = (const float4*)(cb + (size_t)bi1 * D);
    const float4* p2 = (const float4*)(cb + (size_t)bi2 * D);
    float s0 = 0.f, s1 = 0.f, s2 = 0.f;
#pragma unroll
    for (int i = 0; i < 4; ++i) {
        float4 zv = zr[lane + i * 32];
        float4 a = p0[lane + i * 32], b = p1[lane + i * 32], c = p2[lane + i * 32];
        s0 += zv.x * a.x + zv.y * a.y + zv.z * a.z + zv.w * a.w;
        s1 += zv.x * b.x + zv.y * b.y + zv.z * b.z + zv.w * b.w;
        s2 += zv.x * c.x + zv.y * c.y + zv.z * c.z + zv.w * c.w;
    }
#pragma unroll
    for (int off = 16; off; off >>= 1) {
        s0 += __shfl_down_sync(0xffffffffu, s0, off);
        s1 += __shfl_down_sync(0xffffffffu, s1, off);
        s2 += __shfl_down_sync(0xffffffffu, s2, off);
    }
    if (lane == 0) {
        float zsq = g_zsq[warp];
        float d0 = fmaxf(zsq + g_csq[bi0] - 2.f * s0, 0.f);
        float d1 = fmaxf(zsq + g_csq[bi1] - 2.f * s1, 0.f);
        float d2 = fmaxf(zsq + g_csq[bi2] - 2.f * s2, 0.f);
        float bd = d0; int bi = bi0;
        if (d1 < bd || (d1 == bd && bi1 < bi)) { bd = d1; bi = bi1; }
        if (d2 < bd || (d2 == bd && bi2 < bi)) { bd = d2; bi = bi2; }
        g_idx[warp]  = bi;
        g_dmin[warp] = sqrtf(bd);
        g_H[warp]    = __logf(S) - M + T / S;
    }
}

// ---------------- scalar loss reduction ----------------
__global__ void loss_kernel(int N) {
    __shared__ float sd[1024], sh[1024];
    int t = threadIdx.x;
    float a = 0.f, b = 0.f;
    for (int i = t; i < N; i += 1024) { a += g_dmin[i]; b += g_H[i]; }
    sd[t] = a; sh[t] = b;
    __syncthreads();
    for (int off = 512; off; off >>= 1) {
        if (t < off) { sd[t] += sd[t + off]; sh[t] += sh[t + off]; }
        __syncthreads();
    }
    if (t == 0) g_loss = sd[0] / (float)N + 0.1f * sh[0] / (float)N;
}

// ---------------- outputs ----------------
__global__ void out_kernel(const float* __restrict__ cb, const float* __restrict__ yb,
                           const float* __restrict__ et, float* __restrict__ out, int N) {
    int warp = (blockIdx.x * blockDim.x + threadIdx.x) >> 5;
    int lane = threadIdx.x & 31;
    if (warp >= N) return;
    int idx = g_idx[warp];
    const float4* crow = (const float4*)(cb + (size_t)idx * D);
    const float4* yrow = (const float4*)(yb + (size_t)warp * D);
    float4*       qrow = (float4*)(out + (size_t)warp * D);
    float acc = 0.f;
#pragma unroll
    for (int i = 0; i < 4; ++i) {
        float4 cv = crow[lane + i * 32];
        float4 yv = yrow[lane + i * 32];
        qrow[lane + i * 32] = cv;
        float dx = cv.x - yv.x, dy = cv.y - yv.y, dz = cv.z - yv.z, dw = cv.w - yv.w;
        acc += dx * dx + dy * dy + dz * dz + dw * dw;
    }
#pragma unroll
    for (int off = 16; off; off >>= 1) acc += __shfl_down_sync(0xffffffffu, acc, off);
    if (lane == 0) {
        float dev = sqrtf(acc);
        out[(size_t)N * D + warp]     = g_loss;
        out[(size_t)N * D + N + warp] = et[warp] + (dev > 0.01f ? 1.0f : 0.0f);
    }
}

extern "C" void kernel_launch(void* const* d_in, const int* in_sizes, int n_in,
                              void* d_out, int out_size) {
    const float* z  = (const float*)d_in[0];
    const float* yb = (const float*)d_in[1];
    const float* et = (const float*)d_in[2];
    const float* cb = (const float*)d_in[3];
    int N = in_sizes[0] / D;
    int K = in_sizes[3] / D;
    float* out = (float*)d_out;

    cudaFuncSetAttribute(gemm_kernel, cudaFuncAttributeMaxDynamicSharedMemorySize, SMEM_SZ);

    split_kernel<<<(N + K + 7) / 8, 256>>>(z, cb, N, K);
    gemm_kernel<<<256 * KQ, 256, SMEM_SZ>>>();
    mergefix_kernel<<<(N + 7) / 8, 256>>>(z, cb, N);
    loss_kernel<<<1, 1024>>>(N);
    out_kernel<<<(N + 7) / 8, 256>>>(cb, yb, et, out, N);
}

// round 7
// speedup vs baseline: 6.5868x; 1.0006x over previous
#include <cuda_runtime.h>
#include <cuda_bf16.h>
#include <math.h>
#include <stdint.h>

#define D    512
#define NTOK 32768
#define KCB  8192
#define MT   128              // rows per CTA
#define NT   128              // codes per n-iter
#define KC   64               // k per chunk
#define KQ   4                // codebook quarters (work-split)
#define KQ_CODES (KCB / KQ)   // 2048
#define NITER ((KQ_CODES / NT) * (D / KC))   // 16 * 8 = 128
#define A_BYTES (MT * D * 2)            // 131072
#define B_STAGE (NT * KC * 2)           // 16384
#define NSTAGE 4
#define SMEM_SZ (A_BYTES + NSTAGE * B_STAGE) // 196608

// ---------------- device globals ----------------
__device__ __nv_bfloat16 g_zh[(size_t)NTOK * D];
__device__ __nv_bfloat16 g_ch[(size_t)KCB * D];
__device__ float g_zsq[NTOK];
__device__ float g_csq[KCB];
__device__ float g_dmin[NTOK];
__device__ float g_H[NTOK];
__device__ int   g_idx[NTOK];
__device__ float g_loss;
// per (kq, row) partials
__device__ float g_pm[KQ * NTOK], g_ps[KQ * NTOK], g_pt[KQ * NTOK];
__device__ float g_pv0[KQ * NTOK], g_pv1[KQ * NTOK], g_pv2[KQ * NTOK];
__device__ int   g_pi0[KQ * NTOK], g_pi1[KQ * NTOK], g_pi2[KQ * NTOK];

// ---------------- helpers ----------------
__device__ __forceinline__ uint32_t smem_u32(const void* p) {
    uint32_t a;
    asm("{ .reg .u64 t; cvta.to.shared.u64 t, %1; cvt.u32.u64 %0, t; }" : "=r"(a) : "l"(p));
    return a;
}
__device__ __forceinline__ void cp16(uint32_t s, const void* g) {
    asm volatile("cp.async.cg.shared.global [%0], [%1], 16;" :: "r"(s), "l"(g));
}
#define CP_COMMIT()  asm volatile("cp.async.commit_group;" ::: "memory")
#define CP_WAIT(n)   asm volatile("cp.async.wait_group %0;" :: "n"(n) : "memory")

__device__ __forceinline__ void ldsm4(uint32_t& r0, uint32_t& r1, uint32_t& r2, uint32_t& r3, uint32_t a) {
    asm volatile("ldmatrix.sync.aligned.m8n8.x4.shared.b16 {%0,%1,%2,%3}, [%4];"
                 : "=r"(r0), "=r"(r1), "=r"(r2), "=r"(r3) : "r"(a));
}
__device__ __forceinline__ void mma16816(float* c, uint32_t a0, uint32_t a1, uint32_t a2, uint32_t a3,
                                         uint32_t b0, uint32_t b1) {
    asm volatile("mma.sync.aligned.m16n8k16.row.col.f32.bf16.bf16.f32 "
                 "{%0,%1,%2,%3},{%4,%5,%6,%7},{%8,%9},{%0,%1,%2,%3};"
                 : "+f"(c[0]), "+f"(c[1]), "+f"(c[2]), "+f"(c[3])
                 : "r"(a0), "r"(a1), "r"(a2), "r"(a3), "r"(b0), "r"(b1));
}
__device__ __forceinline__ float sqrt_apx(float x) {
    float r; asm("sqrt.approx.f32 %0, %1;" : "=f"(r) : "f"(x)); return r;
}

// ---------------- fused split: z rows then codebook rows ----------------
__global__ void split_kernel(const float* __restrict__ z, const float* __restrict__ cb,
                             int N, int K) {
    int w = (blockIdx.x * blockDim.x + threadIdx.x) >> 5;
    int lane = threadIdx.x & 31;
    if (w >= N + K) return;
    int which = (w >= N);
    int row = which ? (w - N) : w;
    const float* src = which ? cb : z;
    __nv_bfloat16* dst = which ? g_ch : g_zh;
    const float4* p = (const float4*)(src + (size_t)row * D);
    float acc = 0.f;
#pragma unroll
    for (int i = 0; i < 4; ++i) {
        float4 v = p[lane + i * 32];
        acc += v.x * v.x + v.y * v.y + v.z * v.z + v.w * v.w;
        float xs[4] = {v.x, v.y, v.z, v.w};
        size_t base = (size_t)row * D + (lane + i * 32) * 4;
#pragma unroll
        for (int j = 0; j < 4; ++j) dst[base + j] = __float2bfloat16(xs[j]);
    }
#pragma unroll
    for (int off = 16; off; off >>= 1) acc += __shfl_down_sync(0xffffffffu, acc, off);
    if (lane == 0) { if (which) g_csq[row] = acc; else g_zsq[row] = acc; }
}

// ---------------- B chunk loader ----------------
__device__ __forceinline__ void load_b(uint32_t sb, int iter, int tid, int code_base) {
    int nt = iter >> 3, kc = iter & 7;
    uint32_t st = sb + A_BYTES + (uint32_t)(iter & (NSTAGE - 1)) * B_STAGE;
    const __nv_bfloat16* bh = g_ch + (size_t)(code_base + nt * NT) * D + kc * KC;
#pragma unroll
    for (int i = 0; i < 4; ++i) {
        int q = tid + i * 256;
        int r = q >> 3, c16 = q & 7;
        uint32_t off = (uint32_t)(r * 128 + ((c16 * 16) ^ ((r & 7) << 4)));
        cp16(st + off, bh + (size_t)r * D + c16 * 8);
    }
}

// ---------------- main HMMA GEMM + fused epilogue (one K-quarter) ----------------
__global__ void __launch_bounds__(256, 1) gemm_kernel() {
    extern __shared__ __align__(1024) char sm[];
    uint32_t sb = smem_u32(sm);
    int tid = threadIdx.x, lane = tid & 31, wid = tid >> 5;
    int wm = wid & 3, wn = wid >> 2;          // warp grid 4(M) x 2(N); warp tile 32x64
    int mt = blockIdx.x & 255;
    int kq = blockIdx.x >> 8;
    int n0 = mt * MT;
    int code_base = kq * KQ_CODES;

    // ---- load A (z hi, 128x512 bf16) resident, swizzled chunks of [128][64]
    {
        const __nv_bfloat16* zb = g_zh + (size_t)n0 * D;
#pragma unroll
        for (int i = 0; i < 32; ++i) {
            int q = tid + i * 256;
            int kc = q >> 10, u = q & 1023, r = u >> 3, c16 = u & 7;
            uint32_t so = sb + (uint32_t)(kc * 16384 + r * 128 + ((c16 * 16) ^ ((r & 7) << 4)));
            cp16(so, zb + (size_t)r * D + kc * KC + c16 * 8);
        }
    }
    load_b(sb, 0, tid, code_base); CP_COMMIT();
    load_b(sb, 1, tid, code_base); CP_COMMIT();
    load_b(sb, 2, tid, code_base); CP_COMMIT();

    float m1[4], ss[4], tt[4], zs[4];
    float tv[4][3]; int ti[4][3];
#pragma unroll
    for (int s = 0; s < 4; ++s) {
        m1[s] = 60.f; ss[s] = 0.f; tt[s] = 0.f;
        tv[s][0] = tv[s][1] = tv[s][2] = 1e30f;
        ti[s][0] = ti[s][1] = ti[s][2] = 0;
        int row = n0 + wm * 32 + (s >> 1) * 16 + (lane >> 2) + (s & 1) * 8;
        zs[s] = g_zsq[row];
    }

    float acc[2][8][4];
    int laneA_r[2], laneB_r[4];
#pragma unroll
    for (int m = 0; m < 2; ++m)
        laneA_r[m] = wm * 32 + m * 16 + (lane & 7) + ((lane >> 3) & 1) * 8;
#pragma unroll
    for (int p = 0; p < 4; ++p)
        laneB_r[p] = wn * 64 + (p * 2 + ((lane >> 4) & 1)) * 8 + (lane & 7);
    int byteA = ((lane >> 4) & 1) * 16;
    int byteB = ((lane >> 3) & 1) * 16;

    for (int it = 0; it < NITER; ++it) {
        CP_WAIT(2);
        __syncthreads();
        if (it + 3 < NITER) { load_b(sb, it + 3, tid, code_base); CP_COMMIT(); }

        int kc = it & 7;
        uint32_t abase = sb + kc * 16384;
        uint32_t bbase = sb + A_BYTES + (uint32_t)(it & (NSTAGE - 1)) * B_STAGE;

        if (kc == 0) {
#pragma unroll
            for (int m = 0; m < 2; ++m)
#pragma unroll
                for (int n = 0; n < 8; ++n)
#pragma unroll
                    for (int q = 0; q < 4; ++q) acc[m][n][q] = 0.f;
        }

#pragma unroll
        for (int j = 0; j < 4; ++j) {
            uint32_t a[2][4];
#pragma unroll
            for (int m = 0; m < 2; ++m) {
                int r = laneA_r[m];
                uint32_t ad = abase + (uint32_t)(r * 128 + ((j * 32 + byteA) ^ ((r & 7) << 4)));
                ldsm4(a[m][0], a[m][1], a[m][2], a[m][3], ad);
            }
            uint32_t bh[8][2];
#pragma unroll
            for (int p = 0; p < 4; ++p) {
                int r = laneB_r[p];
                uint32_t off = (uint32_t)(r * 128 + ((j * 32 + byteB) ^ ((r & 7) << 4)));
                ldsm4(bh[2 * p][0], bh[2 * p][1], bh[2 * p + 1][0], bh[2 * p + 1][1], bbase + off);
            }
#pragma unroll
            for (int m = 0; m < 2; ++m)
#pragma unroll
                for (int n = 0; n < 8; ++n)
                    mma16816(acc[m][n], a[m][0], a[m][1], a[m][2], a[m][3], bh[n][0], bh[n][1]);
        }

        if (kc == 7) {                        // fused epilogue for this 128-code tile
            int nt = it >> 3;
            int colbase = code_base + nt * NT + wn * 64 + (lane & 3) * 2;
            float csv[16];
#pragma unroll
            for (int n = 0; n < 8; ++n) {
                csv[2 * n]     = __ldg(g_csq + colbase + n * 8);
                csv[2 * n + 1] = __ldg(g_csq + colbase + n * 8 + 1);
            }
#pragma unroll
            for (int m = 0; m < 2; ++m)
#pragma unroll
                for (int n = 0; n < 8; ++n)
#pragma unroll
                    for (int h = 0; h < 2; ++h)
#pragma unroll
                        for (int q = 0; q < 2; ++q) {
                            int s = m * 2 + h;
                            float dot = acc[m][n][h * 2 + q];
                            int code = colbase + n * 8 + q;
                            float d2 = fmaf(-2.f, dot, zs[s] + csv[2 * n + q]);
                            d2 = fmaxf(d2, 1e-6f);
                            float d = sqrt_apx(d2);
                            if (d2 < tv[s][2]) {
                                if (d2 < tv[s][1]) {
                                    tv[s][2] = tv[s][1]; ti[s][2] = ti[s][1];
                                    if (d2 < tv[s][0]) {
                                        tv[s][1] = tv[s][0]; ti[s][1] = ti[s][0];
                                        tv[s][0] = d2; ti[s][0] = code;
                                    } else { tv[s][1] = d2; ti[s][1] = code; }
                                } else { tv[s][2] = d2; ti[s][2] = code; }
                            }
                            bool nm = d < m1[s];
                            float e = __expf(nm ? (d - m1[s]) : (m1[s] - d));
                            if (nm) {
                                ss[s] = fmaf(ss[s], e, 1.f);
                                tt[s] = fmaf(tt[s], e, d);
                                m1[s] = d;
                            } else {
                                ss[s] += e;
                                tt[s] = fmaf(e, d, tt[s]);
                            }
                        }
        }
    }

    // ---- merge 8 warp-partials per row via smem, write one partial per (kq,row)
    __syncthreads();
    float* msm = (float*)(sm + A_BYTES);
    int*   mim = (int*)msm;
#pragma unroll
    for (int s = 0; s < 4; ++s) {
        int row_local = wm * 32 + (s >> 1) * 16 + (lane >> 2) + (s & 1) * 8;
        int base = (row_local * 8 + wn * 4 + (lane & 3)) * 9;
        msm[base + 0] = m1[s]; msm[base + 1] = ss[s]; msm[base + 2] = tt[s];
        msm[base + 3] = tv[s][0]; msm[base + 4] = tv[s][1]; msm[base + 5] = tv[s][2];
        mim[base + 6] = ti[s][0]; mim[base + 7] = ti[s][1]; mim[base + 8] = ti[s][2];
    }
    __syncthreads();
    if (tid < 128) {
        int row = tid;
        float M = 1e30f;
#pragma unroll
        for (int j = 0; j < 8; ++j) M = fminf(M, msm[(row * 8 + j) * 9]);
        float S = 0.f, T = 0.f;
        float bv0 = 1e30f, bv1 = 1e30f, bv2 = 1e30f;
        int bi0 = 0, bi1 = 0, bi2 = 0;
#pragma unroll
        for (int j = 0; j < 8; ++j) {
            int base = (row * 8 + j) * 9;
            float fct = __expf(M - msm[base + 0]);
            S = fmaf(msm[base + 1], fct, S);
            T = fmaf(msm[base + 2], fct, T);
#pragma unroll
            for (int k = 0; k < 3; ++k) {
                float v = msm[base + 3 + k];
                int   ix = mim[base + 6 + k];
                if (v < bv2) {
                    if (v < bv1) {
                        bv2 = bv1; bi2 = bi1;
                        if (v < bv0) { bv1 = bv0; bi1 = bi0; bv0 = v; bi0 = ix; }
                        else         { bv1 = v;  bi1 = ix; }
                    } else { bv2 = v; bi2 = ix; }
                }
            }
        }
        int gp = kq * NTOK + n0 + row;
        g_pm[gp] = M; g_ps[gp] = S; g_pt[gp] = T;
        g_pv0[gp] = bv0; g_pv1[gp] = bv1; g_pv2[gp] = bv2;
        g_pi0[gp] = bi0; g_pi1[gp] = bi1; g_pi2[gp] = bi2;
    }
}

// ---------------- merge 4 K-quarter partials + exact fp32 rescore ----------------
__global__ void mergefix_kernel(const float* __restrict__ z, const float* __restrict__ cb, int N) {
    int warp = (blockIdx.x * blockDim.x + threadIdx.x) >> 5;
    int lane = threadIdx.x & 31;
    if (warp >= N) return;

    // all lanes do the identical merge (broadcast loads)
    float M = 1e30f;
#pragma unroll
    for (int j = 0; j < KQ; ++j) M = fminf(M, g_pm[j * NTOK + warp]);
    float S = 0.f, T = 0.f;
    float bv0 = 1e30f, bv1 = 1e30f, bv2 = 1e30f;
    int bi0 = 0, bi1 = 0, bi2 = 0;
#pragma unroll
    for (int j = 0; j < KQ; ++j) {
        int gp = j * NTOK + warp;
        float fct = __expf(M - g_pm[gp]);
        S = fmaf(g_ps[gp], fct, S);
        T = fmaf(g_pt[gp], fct, T);
        float vs[3] = {g_pv0[gp], g_pv1[gp], g_pv2[gp]};
        int   is[3] = {g_pi0[gp], g_pi1[gp], g_pi2[gp]};
#pragma unroll
        for (int k = 0; k < 3; ++k) {
            float v = vs[k]; int ix = is[k];
            if (v < bv2) {
                if (v < bv1) {
                    bv2 = bv1; bi2 = bi1;
                    if (v < bv0) { bv1 = bv0; bi1 = bi0; bv0 = v; bi0 = ix; }
                    else         { bv1 = v;  bi1 = ix; }
                } else { bv2 = v; bi2 = ix; }
            }
        }
    }

    // exact fp32 rescore of the 3 merged candidates
    const float4* zr = (const float4*)(z + (size_t)warp * D);
    const float4* p0 = (const float4*)(cb + (size_t)bi0 * D);
    const float4* p1 = (const float4*)(cb + (size_t)bi1 * D);
    const float4* p2 = (const float4*)(cb + (size_t)bi2 * D);
    float s0 = 0.f, s1 = 0.f, s2 = 0.f;
#pragma unroll
    for (int i = 0; i < 4; ++i) {
        float4 zv = zr[lane + i * 32];
        float4 a = p0[lane + i * 32], b = p1[lane + i * 32], c = p2[lane + i * 32];
        s0 += zv.x * a.x + zv.y * a.y + zv.z * a.z + zv.w * a.w;
        s1 += zv.x * b.x + zv.y * b.y + zv.z * b.z + zv.w * b.w;
        s2 += zv.x * c.x + zv.y * c.y + zv.z * c.z + zv.w * c.w;
    }
#pragma unroll
    for (int off = 16; off; off >>= 1) {
        s0 += __shfl_down_sync(0xffffffffu, s0, off);
        s1 += __shfl_down_sync(0xffffffffu, s1, off);
        s2 += __shfl_down_sync(0xffffffffu, s2, off);
    }
    if (lane == 0) {
        float zsq = g_zsq[warp];
        float d0 = fmaxf(zsq + g_csq[bi0] - 2.f * s0, 0.f);
        float d1 = fmaxf(zsq + g_csq[bi1] - 2.f * s1, 0.f);
        float d2 = fmaxf(zsq + g_csq[bi2] - 2.f * s2, 0.f);
        float bd = d0; int bi = bi0;
        if (d1 < bd || (d1 == bd && bi1 < bi)) { bd = d1; bi = bi1; }
        if (d2 < bd || (d2 == bd && bi2 < bi)) { bd = d2; bi = bi2; }
        g_idx[warp]  = bi;
        g_dmin[warp] = sqrtf(bd);
        g_H[warp]    = __logf(S) - M + T / S;
    }
}

// ---------------- scalar loss reduction ----------------
__global__ void loss_kernel(int N) {
    __shared__ float sd[1024], sh[1024];
    int t = threadIdx.x;
    float a = 0.f, b = 0.f;
    for (int i = t; i < N; i += 1024) { a += g_dmin[i]; b += g_H[i]; }
    sd[t] = a; sh[t] = b;
    __syncthreads();
    for (int off = 512; off; off >>= 1) {
        if (t < off) { sd[t] += sd[t + off]; sh[t] += sh[t + off]; }
        __syncthreads();
    }
    if (t == 0) g_loss = sd[0] / (float)N + 0.1f * sh[0] / (float)N;
}

// ---------------- outputs ----------------
__global__ void out_kernel(const float* __restrict__ cb, const float* __restrict__ yb,
                           const float* __restrict__ et, float* __restrict__ out, int N) {
    int warp = (blockIdx.x * blockDim.x + threadIdx.x) >> 5;
    int lane = threadIdx.x & 31;
    if (warp >= N) return;
    int idx = g_idx[warp];
    const float4* crow = (const float4*)(cb + (size_t)idx * D);
    const float4* yrow = (const float4*)(yb + (size_t)warp * D);
    float4*       qrow = (float4*)(out + (size_t)warp * D);
    float acc = 0.f;
#pragma unroll
    for (int i = 0; i < 4; ++i) {
        float4 cv = crow[lane + i * 32];
        float4 yv = yrow[lane + i * 32];
        qrow[lane + i * 32] = cv;
        float dx = cv.x - yv.x, dy = cv.y - yv.y, dz = cv.z - yv.z, dw = cv.w - yv.w;
        acc += dx * dx + dy * dy + dz * dz + dw * dw;
    }
#pragma unroll
    for (int off = 16; off; off >>= 1) acc += __shfl_down_sync(0xffffffffu, acc, off);
    if (lane == 0) {
        float dev = sqrtf(acc);
        out[(size_t)N * D + warp]     = g_loss;
        out[(size_t)N * D + N + warp] = et[warp] + (dev > 0.01f ? 1.0f : 0.0f);
    }
}

extern "C" void kernel_launch(void* const* d_in, const int* in_sizes, int n_in,
                              void* d_out, int out_size) {
    const float* z  = (const float*)d_in[0];
    const float* yb = (const float*)d_in[1];
    const float* et = (const float*)d_in[2];
    const float* cb = (const float*)d_in[3];
    int N = in_sizes[0] / D;
    int K = in_sizes[3] / D;
    float* out = (float*)d_out;

    cudaFuncSetAttribute(gemm_kernel, cudaFuncAttributeMaxDynamicSharedMemorySize, SMEM_SZ);

    split_kernel<<<(N + K + 7) / 8, 256>>>(z, cb, N, K);
    gemm_kernel<<<256 * KQ, 256, SMEM_SZ>>>();
    mergefix_kernel<<<(N + 7) / 8, 256>>>(z, cb, N);
    loss_kernel<<<1, 1024>>>(N);
    out_kernel<<<(N + 7) / 8, 256>>>(cb, yb, et, out, N);
}